// round 1
// baseline (speedup 1.0000x reference)
#include <cuda_runtime.h>
#include <cuda_bf16.h>
#include <math.h>

// Problem constants (fixed by the reference)
#define BATCH   2
#define SEQ     2048
#define EMB     1024
#define NHEAD   16
#define HDIM    64
#define QKVN    3072          // 3*EMB
#define MROWS   (BATCH*SEQ)   // 4096
#define TINY_F  1.17549435e-38f
#define SCALE_Q 0.125f        // 1/sqrt(64)
#define BIGNEG  -9000000000000000.0f
#define BIGPOS   9000000000000000.0f

// Scratch for qkv projection: [B*S, 3072] row-major
__device__ float g_qkv[(size_t)MROWS * QKVN];

// ---------------------------------------------------------------------------
// Kernel 1: qkv = x @ W_qkv + b_qkv    (M=4096, K=1024, N=3072, fp32)
// 128x128 tile, BK=8, 256 threads, 8x8 per thread, register prefetch.
// ---------------------------------------------------------------------------
__global__ void __launch_bounds__(256, 2)
qkv_gemm_kernel(const float* __restrict__ A,     // x [4096,1024]
                const float* __restrict__ B,     // W [1024,3072]
                const float* __restrict__ bias)  // [3072]
{
    const int K = EMB, N = QKVN;
    __shared__ float As[8][128];
    __shared__ float Bs[8][128];

    const int tid = threadIdx.x;
    const int bn = blockIdx.x * 128;
    const int bm = blockIdx.y * 128;
    const int tx = tid & 15;       // 0..15 -> 8 cols each
    const int ty = tid >> 4;       // 0..15 -> 8 rows each

    // A tile loader: row ar (0..127), 4 floats at col aq
    const int ar = tid >> 1;
    const int aq = (tid & 1) * 4;
    // B tile loader: row br (0..7), 4 floats at col bc
    const int br = tid >> 5;
    const int bc = (tid & 31) * 4;

    const float* Aptr = A + (size_t)(bm + ar) * K + aq;
    const float* Bptr = B + (size_t)br * N + bn + bc;

    float acc[8][8];
#pragma unroll
    for (int i = 0; i < 8; i++)
#pragma unroll
        for (int j = 0; j < 8; j++) acc[i][j] = 0.0f;

    float4 a4 = *(const float4*)(Aptr);
    float4 b4 = *(const float4*)(Bptr);

    for (int k0 = 0; k0 < K; k0 += 8) {
        __syncthreads();
        As[aq + 0][ar] = a4.x;
        As[aq + 1][ar] = a4.y;
        As[aq + 2][ar] = a4.z;
        As[aq + 3][ar] = a4.w;
        *(float4*)&Bs[br][bc] = b4;
        __syncthreads();

        if (k0 + 8 < K) {
            a4 = *(const float4*)(Aptr + k0 + 8);
            b4 = *(const float4*)(Bptr + (size_t)(k0 + 8) * N);
        }

#pragma unroll
        for (int kk = 0; kk < 8; kk++) {
            float a[8], b[8];
            *(float4*)(a)     = *(const float4*)&As[kk][ty * 8];
            *(float4*)(a + 4) = *(const float4*)&As[kk][ty * 8 + 4];
            *(float4*)(b)     = *(const float4*)&Bs[kk][tx * 8];
            *(float4*)(b + 4) = *(const float4*)&Bs[kk][tx * 8 + 4];
#pragma unroll
            for (int i = 0; i < 8; i++)
#pragma unroll
                for (int j = 0; j < 8; j++)
                    acc[i][j] += a[i] * b[j];
        }
    }

    // Epilogue: add bias, write to g_qkv
    float bv[8];
    *(float4*)(bv)     = *(const float4*)(bias + bn + tx * 8);
    *(float4*)(bv + 4) = *(const float4*)(bias + bn + tx * 8 + 4);
#pragma unroll
    for (int i = 0; i < 8; i++) {
        const int row = bm + ty * 8 + i;
        float* Cp = g_qkv + (size_t)row * N + bn + tx * 8;
        float4 r0 = make_float4(acc[i][0] + bv[0], acc[i][1] + bv[1],
                                acc[i][2] + bv[2], acc[i][3] + bv[3]);
        float4 r1 = make_float4(acc[i][4] + bv[4], acc[i][5] + bv[5],
                                acc[i][6] + bv[6], acc[i][7] + bv[7]);
        *(float4*)(Cp)     = r0;
        *(float4*)(Cp + 4) = r1;
    }
}

// ---------------------------------------------------------------------------
// Kernel 2: flash attention with weighted-logit bias, fp32.
// Grid: (S/64, H, B). Block: 128 threads. Each thread: 8 rows x 4 cols.
// Smem: Qs[64][68], Kt[64][64] (d-major, 16B xor-swizzled), Vs[64][68],
//       Ps[64][68], wsc[64], wvl[64].
// logit = fmaf(qk, wsc[key], wvl[key]):
//   w==0 -> (0, -9e15); w==1 -> (0, +9e15); else (0.125, log(w+TINY)).
// ---------------------------------------------------------------------------
#define SMEM_FLOATS (64*68 + 64*64 + 64*68 + 64*68 + 64 + 64)
#define SMEM_BYTES  (SMEM_FLOATS * 4)

#define ACC4(si, q, c)          \
    do {                        \
        si[0] += (q) * (c).x;   \
        si[1] += (q) * (c).y;   \
        si[2] += (q) * (c).z;   \
        si[3] += (q) * (c).w;   \
    } while (0)

__global__ void __launch_bounds__(128, 3)
attn_kernel(const float* __restrict__ weights,  // [B, S]
            float* __restrict__ out)            // [B, S, E]
{
    extern __shared__ float sm[];
    float* Qs  = sm;                 // 64*68
    float* Kt  = Qs  + 64 * 68;      // 64*64, row = d, col = key (swizzled)
    float* Vs  = Kt  + 64 * 64;      // 64*68, row = key, col = d
    float* Ps  = Vs  + 64 * 68;      // 64*68, row = query, col = key
    float* wsc = Ps  + 64 * 68;      // 64
    float* wvl = wsc + 64;           // 64

    const int tid = threadIdx.x;
    const int tx = tid & 15;         // col group: 4 cols
    const int ty = tid >> 4;         // row group: 8 rows
    const int qt = blockIdx.x;
    const int h  = blockIdx.y;
    const int b  = blockIdx.z;

    const float* qbase = g_qkv + (size_t)(b * SEQ + qt * 64) * QKVN + h * 192;

    // Load Q tile [64 x 64] (natural layout)
#pragma unroll
    for (int i = 0; i < 8; i++) {
        const int f = tid + 128 * i;
        const int r = f >> 4, c4 = f & 15;
        float4 v = *(const float4*)(qbase + (size_t)r * QKVN + c4 * 4);
        *(float4*)&Qs[r * 68 + c4 * 4] = v;
    }

    float m[8], l[8], o[8][4];
#pragma unroll
    for (int i = 0; i < 8; i++) {
        m[i] = -1e30f;
        l[i] = 0.0f;
        o[i][0] = o[i][1] = o[i][2] = o[i][3] = 0.0f;
    }

    const float* wrow = weights + b * SEQ;

    for (int t = 0; t < SEQ / 64; t++) {
        const float* kvb = g_qkv + (size_t)(b * SEQ + t * 64) * QKVN + h * 192;
        __syncthreads();   // previous tile fully consumed

        // K tile -> Kt[d][key], transposed with 16B xor swizzle per row
#pragma unroll
        for (int i = 0; i < 8; i++) {
            const int f = tid + 128 * i;
            const int key = f >> 4, c4 = f & 15;
            float4 v = *(const float4*)(kvb + (size_t)key * QKVN + 64 + c4 * 4);
            const int k2 = key >> 2, kr = key & 3;
            const int pcol = (((k2) ^ c4) << 2) + kr;   // swz(d)=d>>2, d=4*c4+u
            const int d0 = c4 * 4;
            Kt[(d0 + 0) * 64 + pcol] = v.x;
            Kt[(d0 + 1) * 64 + pcol] = v.y;
            Kt[(d0 + 2) * 64 + pcol] = v.z;
            Kt[(d0 + 3) * 64 + pcol] = v.w;
        }
        // V tile -> Vs[key][d] (natural)
#pragma unroll
        for (int i = 0; i < 8; i++) {
            const int f = tid + 128 * i;
            const int key = f >> 4, c4 = f & 15;
            float4 v = *(const float4*)(kvb + (size_t)key * QKVN + 128 + c4 * 4);
            *(float4*)&Vs[key * 68 + c4 * 4] = v;
        }
        // Per-key logit transform
        if (tid < 64) {
            const float w = wrow[t * 64 + tid];
            const bool z  = (w == 0.0f);
            const bool on = (w == 1.0f);
            wsc[tid] = (z || on) ? 0.0f : SCALE_Q;
            wvl[tid] = z ? BIGNEG : (on ? BIGPOS : logf(w + TINY_F));
        }
        __syncthreads();

        // S = Q K^T  (8x4 per thread)
        float s[8][4];
#pragma unroll
        for (int i = 0; i < 8; i++)
            s[i][0] = s[i][1] = s[i][2] = s[i][3] = 0.0f;

#pragma unroll 4
        for (int k4 = 0; k4 < 64; k4 += 4) {
            float4 kv0 = *(const float4*)&Kt[(k4 + 0) * 64 + ((tx ^ ((k4 + 0) >> 2)) << 2)];
            float4 kv1 = *(const float4*)&Kt[(k4 + 1) * 64 + ((tx ^ ((k4 + 1) >> 2)) << 2)];
            float4 kv2 = *(const float4*)&Kt[(k4 + 2) * 64 + ((tx ^ ((k4 + 2) >> 2)) << 2)];
            float4 kv3 = *(const float4*)&Kt[(k4 + 3) * 64 + ((tx ^ ((k4 + 3) >> 2)) << 2)];
#pragma unroll
            for (int i = 0; i < 8; i++) {
                float4 q = *(const float4*)&Qs[(ty * 8 + i) * 68 + k4];
                ACC4(s[i], q.x, kv0);
                ACC4(s[i], q.y, kv1);
                ACC4(s[i], q.z, kv2);
                ACC4(s[i], q.w, kv3);
            }
        }

        // logit transform + online softmax
        const float4 wsv = *(const float4*)&wsc[tx * 4];
        const float4 wvv = *(const float4*)&wvl[tx * 4];
#pragma unroll
        for (int i = 0; i < 8; i++) {
            s[i][0] = fmaf(s[i][0], wsv.x, wvv.x);
            s[i][1] = fmaf(s[i][1], wsv.y, wvv.y);
            s[i][2] = fmaf(s[i][2], wsv.z, wvv.z);
            s[i][3] = fmaf(s[i][3], wsv.w, wvv.w);

            float mx = fmaxf(fmaxf(s[i][0], s[i][1]), fmaxf(s[i][2], s[i][3]));
            mx = fmaxf(mx, __shfl_xor_sync(0xffffffffu, mx, 1));
            mx = fmaxf(mx, __shfl_xor_sync(0xffffffffu, mx, 2));
            mx = fmaxf(mx, __shfl_xor_sync(0xffffffffu, mx, 4));
            mx = fmaxf(mx, __shfl_xor_sync(0xffffffffu, mx, 8));

            const float mnew = fmaxf(m[i], mx);
            const float corr = __expf(m[i] - mnew);
            m[i] = mnew;

            s[i][0] = __expf(s[i][0] - mnew);
            s[i][1] = __expf(s[i][1] - mnew);
            s[i][2] = __expf(s[i][2] - mnew);
            s[i][3] = __expf(s[i][3] - mnew);

            float rs = (s[i][0] + s[i][1]) + (s[i][2] + s[i][3]);
            rs += __shfl_xor_sync(0xffffffffu, rs, 1);
            rs += __shfl_xor_sync(0xffffffffu, rs, 2);
            rs += __shfl_xor_sync(0xffffffffu, rs, 4);
            rs += __shfl_xor_sync(0xffffffffu, rs, 8);

            l[i] = l[i] * corr + rs;
            o[i][0] *= corr;
            o[i][1] *= corr;
            o[i][2] *= corr;
            o[i][3] *= corr;

            *(float4*)&Ps[(ty * 8 + i) * 68 + tx * 4] =
                make_float4(s[i][0], s[i][1], s[i][2], s[i][3]);
        }
        __syncthreads();

        // O += P V
#pragma unroll 4
        for (int k4 = 0; k4 < 64; k4 += 4) {
            float4 vv0 = *(const float4*)&Vs[(k4 + 0) * 68 + tx * 4];
            float4 vv1 = *(const float4*)&Vs[(k4 + 1) * 68 + tx * 4];
            float4 vv2 = *(const float4*)&Vs[(k4 + 2) * 68 + tx * 4];
            float4 vv3 = *(const float4*)&Vs[(k4 + 3) * 68 + tx * 4];
#pragma unroll
            for (int i = 0; i < 8; i++) {
                float4 p = *(const float4*)&Ps[(ty * 8 + i) * 68 + k4];
                ACC4(o[i], p.x, vv0);
                ACC4(o[i], p.y, vv1);
                ACC4(o[i], p.z, vv2);
                ACC4(o[i], p.w, vv3);
            }
        }
    }

    // Epilogue: normalize and write out[b, s, h*64 + d]
#pragma unroll
    for (int i = 0; i < 8; i++) {
        const float inv = 1.0f / l[i];
        const int row = b * SEQ + qt * 64 + ty * 8 + i;
        float4 r = make_float4(o[i][0] * inv, o[i][1] * inv,
                               o[i][2] * inv, o[i][3] * inv);
        *(float4*)(out + (size_t)row * EMB + h * 64 + tx * 4) = r;
    }
}

// ---------------------------------------------------------------------------
extern "C" void kernel_launch(void* const* d_in, const int* in_sizes, int n_in,
                              void* d_out, int out_size)
{
    const float* x    = (const float*)d_in[0];   // [2,2048,1024]
    const float* w    = (const float*)d_in[1];   // [2,2048]
    const float* Wqkv = (const float*)d_in[2];   // [1024,3072]
    const float* bqkv = (const float*)d_in[3];   // [3072]
    float* out = (float*)d_out;                  // [2,2048,1024]

    dim3 g1(QKVN / 128, MROWS / 128);            // (24, 32)
    qkv_gemm_kernel<<<g1, 256>>>(x, Wqkv, bqkv);

    cudaFuncSetAttribute(attn_kernel,
                         cudaFuncAttributeMaxDynamicSharedMemorySize,
                         SMEM_BYTES);
    dim3 g2(SEQ / 64, NHEAD, BATCH);             // (32, 16, 2)
    attn_kernel<<<g2, 128, SMEM_BYTES>>>(w, out);
}

// round 3
// speedup vs baseline: 2.3369x; 2.3369x over previous
#include <cuda_runtime.h>
#include <cuda_bf16.h>
#include <math.h>
#include <stdint.h>

// Problem constants
#define BATCH   2
#define SEQ     2048
#define EMB     1024
#define NHEAD   16
#define QKVN    3072
#define MROWS   4096
#define TINY_F  1.17549435e-38f
#define SCALE_Q 0.125f
#define BIGNEG  -9000000000000000.0f
#define BIGPOS   9000000000000000.0f

// Global scratch: split-bf16 representations
__device__ __nv_bfloat16 g_x_hi[(size_t)MROWS * EMB];
__device__ __nv_bfloat16 g_x_lo[(size_t)MROWS * EMB];
__device__ __nv_bfloat16 g_w_hi[(size_t)EMB * QKVN];
__device__ __nv_bfloat16 g_w_lo[(size_t)EMB * QKVN];
__device__ __nv_bfloat16 g_qkv_hi[(size_t)MROWS * QKVN];
__device__ __nv_bfloat16 g_qkv_lo[(size_t)MROWS * QKVN];

// ---------------------------------------------------------------------------
// PTX helpers
// ---------------------------------------------------------------------------
#define MMA_BF16(c, a0, a1, a2, a3, b0, b1)                                  \
    asm volatile(                                                            \
        "mma.sync.aligned.m16n8k16.row.col.f32.bf16.bf16.f32 "               \
        "{%0,%1,%2,%3}, {%4,%5,%6,%7}, {%8,%9}, {%0,%1,%2,%3};"              \
        : "+f"((c)[0]), "+f"((c)[1]), "+f"((c)[2]), "+f"((c)[3])             \
        : "r"(a0), "r"(a1), "r"(a2), "r"(a3), "r"(b0), "r"(b1))

#define LDSM_X4(r0, r1, r2, r3, a)                                           \
    asm volatile("ldmatrix.sync.aligned.m8n8.x4.shared.b16 {%0,%1,%2,%3}, [%4];" \
        : "=r"(r0), "=r"(r1), "=r"(r2), "=r"(r3) : "r"(a))

#define LDSM_X4_T(r0, r1, r2, r3, a)                                         \
    asm volatile("ldmatrix.sync.aligned.m8n8.x4.trans.shared.b16 {%0,%1,%2,%3}, [%4];" \
        : "=r"(r0), "=r"(r1), "=r"(r2), "=r"(r3) : "r"(a))

#define CPA16(dst_u32, src_ptr)                                              \
    asm volatile("cp.async.cg.shared.global [%0], [%1], 16;"                 \
                 :: "r"(dst_u32), "l"(src_ptr))
#define CPA_COMMIT() asm volatile("cp.async.commit_group;")
#define CPA_WAIT1()  asm volatile("cp.async.wait_group 1;")
#define CPA_WAIT0()  asm volatile("cp.async.wait_group 0;")

// split two floats into packed hi/lo bf16x2
__device__ __forceinline__ void split2(float x, float y,
                                       uint32_t& hi, uint32_t& lo)
{
    __nv_bfloat162 h = __floats2bfloat162_rn(x, y);
    float rx = x - __bfloat162float(h.x);
    float ry = y - __bfloat162float(h.y);
    __nv_bfloat162 l = __floats2bfloat162_rn(rx, ry);
    hi = *reinterpret_cast<uint32_t*>(&h);
    lo = *reinterpret_cast<uint32_t*>(&l);
}

// ---------------------------------------------------------------------------
// Split kernels: fp32 -> (hi, lo) bf16
// ---------------------------------------------------------------------------
__device__ __forceinline__ void split_store(const float4* in, uint2* hi,
                                            uint2* lo, int i)
{
    float4 v = in[i];
    uint2 uh, ul;
    split2(v.x, v.y, uh.x, ul.x);
    split2(v.z, v.w, uh.y, ul.y);
    hi[i] = uh;
    lo[i] = ul;
}

__global__ void split_x_kernel(const float4* __restrict__ in)
{
    int i = blockIdx.x * blockDim.x + threadIdx.x;
    if (i < MROWS * EMB / 4)
        split_store(in, (uint2*)g_x_hi, (uint2*)g_x_lo, i);
}

__global__ void split_w_kernel(const float4* __restrict__ in)
{
    int i = blockIdx.x * blockDim.x + threadIdx.x;
    if (i < EMB * QKVN / 4)
        split_store(in, (uint2*)g_w_hi, (uint2*)g_w_lo, i);
}

// ---------------------------------------------------------------------------
// Kernel 1: qkv = x @ W + b, bf16x3 mma. CTA 128x128, BK=32, 256 threads,
// 8 warps (4x2), warp tile 32x64. cp.async double buffered.
// ---------------------------------------------------------------------------
#define GA_STR 40                       // halves per A smem row (pad 32->40)
#define GB_STR 136                      // halves per B smem row (pad 128->136)
#define GA_H   (128 * GA_STR)           // 5120
#define GB_H   (32 * GB_STR)            // 4352
#define GBUF_H (2 * GA_H + 2 * GB_H)    // halves per buffer
#define GEMM_SMEM_BYTES (2 * GBUF_H * 2)  // 75776

__global__ void __launch_bounds__(256)
qkv_gemm(const float* __restrict__ bias)
{
    extern __shared__ __nv_bfloat16 sh[];
    const uint32_t sbase = (uint32_t)__cvta_generic_to_shared(sh);

    const int tid  = threadIdx.x;
    const int lane = tid & 31, wid = tid >> 5;
    const int g = lane >> 2, tig = lane & 3;
    const int wr = wid >> 1, wc = wid & 1;
    const int bn = blockIdx.x * 128, bm = blockIdx.y * 128;

    const uint32_t OAh = 0, OAl = GA_H * 2;
    const uint32_t OBh = 2 * GA_H * 2, OBl = (2 * GA_H + GB_H) * 2;
    const uint32_t BUFB = GBUF_H * 2;

    float acc[2][8][4];
#pragma unroll
    for (int mt = 0; mt < 2; mt++)
#pragma unroll
        for (int j = 0; j < 8; j++)
#pragma unroll
            for (int q = 0; q < 4; q++) acc[mt][j][q] = 0.0f;

    // ldmatrix lane-address components
    const int a_row = (lane & 7) + 8 * ((lane >> 3) & 1);
    const int a_col = 8 * (lane >> 4);
    const int b_row = lane & 15;
    const int b_col = 8 * (lane >> 4);

    // tile issue lambda (macro-style)
#define GEMM_ISSUE(buf, kt)                                                  \
    do {                                                                     \
        const uint32_t sb = sbase + (buf) * BUFB;                            \
        _Pragma("unroll")                                                    \
        for (int i = 0; i < 2; i++) {                                        \
            int ch = tid + 256 * i;                                          \
            int r = ch >> 2, sg = ch & 3;                                    \
            size_t go = (size_t)(bm + r) * EMB + (kt) * 32 + sg * 8;         \
            uint32_t d = sb + (uint32_t)(r * GA_STR + sg * 8) * 2;           \
            CPA16(d + OAh, g_x_hi + go);                                     \
            CPA16(d + OAl, g_x_lo + go);                                     \
        }                                                                    \
        _Pragma("unroll")                                                    \
        for (int i = 0; i < 2; i++) {                                        \
            int ch = tid + 256 * i;                                          \
            int r = ch >> 4, sg = ch & 15;                                   \
            size_t go = (size_t)((kt) * 32 + r) * QKVN + bn + sg * 8;        \
            uint32_t d = sb + (uint32_t)(r * GB_STR + sg * 8) * 2;           \
            CPA16(d + OBh, g_w_hi + go);                                     \
            CPA16(d + OBl, g_w_lo + go);                                     \
        }                                                                    \
    } while (0)

    GEMM_ISSUE(0, 0);
    CPA_COMMIT();

    for (int kt = 0; kt < 32; kt++) {
        const int buf = kt & 1;
        if (kt < 31) {
            GEMM_ISSUE(buf ^ 1, kt + 1);
            CPA_COMMIT();
            CPA_WAIT1();
        } else {
            CPA_WAIT0();
        }
        __syncthreads();

        const uint32_t sb = sbase + buf * BUFB;
#pragma unroll
        for (int ks = 0; ks < 2; ks++) {
            const int k0 = ks * 16;
            uint32_t ah[2][4], al[2][4];
#pragma unroll
            for (int mt = 0; mt < 2; mt++) {
                const uint32_t off =
                    (uint32_t)((wr * 32 + mt * 16 + a_row) * GA_STR + k0 + a_col) * 2;
                LDSM_X4(ah[mt][0], ah[mt][1], ah[mt][2], ah[mt][3], sb + OAh + off);
                LDSM_X4(al[mt][0], al[mt][1], al[mt][2], al[mt][3], sb + OAl + off);
            }
#pragma unroll
            for (int jp = 0; jp < 4; jp++) {
                const uint32_t off =
                    (uint32_t)((k0 + b_row) * GB_STR + wc * 64 + jp * 16 + b_col) * 2;
                uint32_t bh0, bh1, bh2, bh3, bl0, bl1, bl2, bl3;
                LDSM_X4_T(bh0, bh1, bh2, bh3, sb + OBh + off);
                LDSM_X4_T(bl0, bl1, bl2, bl3, sb + OBl + off);
#pragma unroll
                for (int mt = 0; mt < 2; mt++) {
                    MMA_BF16(acc[mt][2 * jp], ah[mt][0], ah[mt][1], ah[mt][2], ah[mt][3], bh0, bh1);
                    MMA_BF16(acc[mt][2 * jp], ah[mt][0], ah[mt][1], ah[mt][2], ah[mt][3], bl0, bl1);
                    MMA_BF16(acc[mt][2 * jp], al[mt][0], al[mt][1], al[mt][2], al[mt][3], bh0, bh1);
                    MMA_BF16(acc[mt][2 * jp + 1], ah[mt][0], ah[mt][1], ah[mt][2], ah[mt][3], bh2, bh3);
                    MMA_BF16(acc[mt][2 * jp + 1], ah[mt][0], ah[mt][1], ah[mt][2], ah[mt][3], bl2, bl3);
                    MMA_BF16(acc[mt][2 * jp + 1], al[mt][0], al[mt][1], al[mt][2], al[mt][3], bh2, bh3);
                }
            }
        }
        __syncthreads();
    }

    // Epilogue: add bias, split to hi/lo bf16, store
#pragma unroll
    for (int mt = 0; mt < 2; mt++) {
        const int row0 = bm + wr * 32 + mt * 16 + g;
#pragma unroll
        for (int j = 0; j < 8; j++) {
            const int col = bn + wc * 64 + j * 8 + 2 * tig;
            const float2 bb = *(const float2*)(bias + col);
            uint32_t h0, l0, h1, l1;
            split2(acc[mt][j][0] + bb.x, acc[mt][j][1] + bb.y, h0, l0);
            split2(acc[mt][j][2] + bb.x, acc[mt][j][3] + bb.y, h1, l1);
            *(uint32_t*)(g_qkv_hi + (size_t)row0 * QKVN + col)       = h0;
            *(uint32_t*)(g_qkv_lo + (size_t)row0 * QKVN + col)       = l0;
            *(uint32_t*)(g_qkv_hi + (size_t)(row0 + 8) * QKVN + col) = h1;
            *(uint32_t*)(g_qkv_lo + (size_t)(row0 + 8) * QKVN + col) = l1;
        }
    }
#undef GEMM_ISSUE
}

// ---------------------------------------------------------------------------
// Kernel 2: flash attention, bf16x3 mma. Grid (S/64, H, B), 128 threads,
// warp w owns 16 query rows. Softmax fp32; P stays in registers.
// ---------------------------------------------------------------------------
#define TS2 72                               // halves per smem row
#define TILE_H (64 * TS2)                    // halves per tile
#define BQh 0
#define BQl (1 * TILE_H * 2)
#define BKh (2 * TILE_H * 2)
#define BKl (3 * TILE_H * 2)
#define BVh (4 * TILE_H * 2)
#define BVl (5 * TILE_H * 2)
#define ATTN_W_OFF (6 * TILE_H)              // in halves
#define ATTN_SMEM_BYTES (6 * TILE_H * 2 + 2 * 64 * 4)   // 55808

__global__ void __launch_bounds__(128)
attn_bf16(const float* __restrict__ weights,  // [B, S]
          float* __restrict__ out)            // [B, S, E]
{
    extern __shared__ __nv_bfloat16 sh[];
    float* wsc = (float*)(sh + ATTN_W_OFF);
    float* wvl = wsc + 64;
    const uint32_t sbase = (uint32_t)__cvta_generic_to_shared(sh);

    const int tid  = threadIdx.x;
    const int lane = tid & 31, wrp = tid >> 5;
    const int g = lane >> 2, tig = lane & 3;
    const int qt = blockIdx.x, h = blockIdx.y, b = blockIdx.z;

    const int a_row = (lane & 7) + 8 * ((lane >> 3) & 1);
    const int a_col = 8 * (lane >> 4);
    const int k_row = (lane & 7) + 8 * (lane >> 4);
    const int k_col = 8 * ((lane >> 3) & 1);

    // ---- load Q tile (hi+lo) via cp.async ----
#pragma unroll
    for (int i = 0; i < 4; i++) {
        const int ch = tid + 128 * i;
        const int r = ch >> 3, sg = ch & 7;
        const size_t go = (size_t)(b * SEQ + qt * 64 + r) * QKVN + h * 192 + sg * 8;
        const uint32_t d = (uint32_t)(r * TS2 + sg * 8) * 2;
        CPA16(sbase + BQh + d, g_qkv_hi + go);
        CPA16(sbase + BQl + d, g_qkv_lo + go);
    }
    CPA_COMMIT();
    CPA_WAIT0();
    __syncthreads();

    // Q fragments -> registers (loop invariant)
    uint32_t qh[4][4], ql[4][4];
#pragma unroll
    for (int kk = 0; kk < 4; kk++) {
        const uint32_t off =
            (uint32_t)((16 * wrp + a_row) * TS2 + kk * 16 + a_col) * 2;
        LDSM_X4(qh[kk][0], qh[kk][1], qh[kk][2], qh[kk][3], sbase + BQh + off);
        LDSM_X4(ql[kk][0], ql[kk][1], ql[kk][2], ql[kk][3], sbase + BQl + off);
    }

    float m0 = -1e30f, m1 = -1e30f, l0 = 0.0f, l1 = 0.0f;
    float o[8][4];
#pragma unroll
    for (int j = 0; j < 8; j++)
        o[j][0] = o[j][1] = o[j][2] = o[j][3] = 0.0f;

    const float* wrow = weights + b * SEQ;

    for (int t = 0; t < SEQ / 64; t++) {
        __syncthreads();   // previous K/V tiles + w arrays fully consumed

        // ---- issue K/V (hi+lo) cp.async ----
#pragma unroll
        for (int i = 0; i < 4; i++) {
            const int ch = tid + 128 * i;
            const int r = ch >> 3, sg = ch & 7;
            const size_t go = (size_t)(b * SEQ + t * 64 + r) * QKVN + h * 192 + sg * 8;
            const uint32_t d = (uint32_t)(r * TS2 + sg * 8) * 2;
            CPA16(sbase + BKh + d, g_qkv_hi + go + 64);
            CPA16(sbase + BKl + d, g_qkv_lo + go + 64);
            CPA16(sbase + BVh + d, g_qkv_hi + go + 128);
            CPA16(sbase + BVl + d, g_qkv_lo + go + 128);
        }
        CPA_COMMIT();

        if (tid < 64) {
            const float wv = wrow[t * 64 + tid];
            const bool z  = (wv == 0.0f);
            const bool on = (wv == 1.0f);
            wsc[tid] = (z || on) ? 0.0f : SCALE_Q;
            wvl[tid] = z ? BIGNEG : (on ? BIGPOS : logf(wv + TINY_F));
        }
        CPA_WAIT0();
        __syncthreads();

        // ---- S = Q K^T (bf16x3) ----
        float s[8][4];
#pragma unroll
        for (int j = 0; j < 8; j++)
            s[j][0] = s[j][1] = s[j][2] = s[j][3] = 0.0f;

#pragma unroll
        for (int kk = 0; kk < 4; kk++) {
#pragma unroll
            for (int jp = 0; jp < 4; jp++) {
                const uint32_t off =
                    (uint32_t)((jp * 16 + k_row) * TS2 + kk * 16 + k_col) * 2;
                uint32_t kh0, kh1, kh2, kh3, kl0, kl1, kl2, kl3;
                LDSM_X4(kh0, kh1, kh2, kh3, sbase + BKh + off);
                LDSM_X4(kl0, kl1, kl2, kl3, sbase + BKl + off);
                MMA_BF16(s[2 * jp],     qh[kk][0], qh[kk][1], qh[kk][2], qh[kk][3], kh0, kh1);
                MMA_BF16(s[2 * jp],     qh[kk][0], qh[kk][1], qh[kk][2], qh[kk][3], kl0, kl1);
                MMA_BF16(s[2 * jp],     ql[kk][0], ql[kk][1], ql[kk][2], ql[kk][3], kh0, kh1);
                MMA_BF16(s[2 * jp + 1], qh[kk][0], qh[kk][1], qh[kk][2], qh[kk][3], kh2, kh3);
                MMA_BF16(s[2 * jp + 1], qh[kk][0], qh[kk][1], qh[kk][2], qh[kk][3], kl2, kl3);
                MMA_BF16(s[2 * jp + 1], ql[kk][0], ql[kk][1], ql[kk][2], ql[kk][3], kh2, kh3);
            }
        }

        // ---- logit transform + online softmax (fp32) ----
        float mx0 = -1e30f, mx1 = -1e30f;
#pragma unroll
        for (int j = 0; j < 8; j++) {
            const float2 ws = *(const float2*)&wsc[j * 8 + 2 * tig];
            const float2 wv = *(const float2*)&wvl[j * 8 + 2 * tig];
            s[j][0] = fmaf(s[j][0], ws.x, wv.x);
            s[j][1] = fmaf(s[j][1], ws.y, wv.y);
            s[j][2] = fmaf(s[j][2], ws.x, wv.x);
            s[j][3] = fmaf(s[j][3], ws.y, wv.y);
            mx0 = fmaxf(mx0, fmaxf(s[j][0], s[j][1]));
            mx1 = fmaxf(mx1, fmaxf(s[j][2], s[j][3]));
        }
        mx0 = fmaxf(mx0, __shfl_xor_sync(0xffffffffu, mx0, 1));
        mx0 = fmaxf(mx0, __shfl_xor_sync(0xffffffffu, mx0, 2));
        mx1 = fmaxf(mx1, __shfl_xor_sync(0xffffffffu, mx1, 1));
        mx1 = fmaxf(mx1, __shfl_xor_sync(0xffffffffu, mx1, 2));

        const float mn0 = fmaxf(m0, mx0), mn1 = fmaxf(m1, mx1);
        const float c0 = __expf(m0 - mn0), c1 = __expf(m1 - mn1);
        m0 = mn0; m1 = mn1;

        float rs0 = 0.0f, rs1 = 0.0f;
#pragma unroll
        for (int j = 0; j < 8; j++) {
            s[j][0] = __expf(s[j][0] - m0);
            s[j][1] = __expf(s[j][1] - m0);
            s[j][2] = __expf(s[j][2] - m1);
            s[j][3] = __expf(s[j][3] - m1);
            rs0 += s[j][0] + s[j][1];
            rs1 += s[j][2] + s[j][3];
        }
        rs0 += __shfl_xor_sync(0xffffffffu, rs0, 1);
        rs0 += __shfl_xor_sync(0xffffffffu, rs0, 2);
        rs1 += __shfl_xor_sync(0xffffffffu, rs1, 1);
        rs1 += __shfl_xor_sync(0xffffffffu, rs1, 2);

        l0 = l0 * c0 + rs0;
        l1 = l1 * c1 + rs1;
#pragma unroll
        for (int j = 0; j < 8; j++) {
            o[j][0] *= c0; o[j][1] *= c0;
            o[j][2] *= c1; o[j][3] *= c1;
        }

        // ---- O += P V (bf16x3; P packed register-to-register) ----
#pragma unroll
        for (int kk = 0; kk < 4; kk++) {
            uint32_t ph[4], pl[4];
            split2(s[2 * kk][0],     s[2 * kk][1],     ph[0], pl[0]);
            split2(s[2 * kk][2],     s[2 * kk][3],     ph[1], pl[1]);
            split2(s[2 * kk + 1][0], s[2 * kk + 1][1], ph[2], pl[2]);
            split2(s[2 * kk + 1][2], s[2 * kk + 1][3], ph[3], pl[3]);
#pragma unroll
            for (int jp = 0; jp < 4; jp++) {
                const uint32_t off =
                    (uint32_t)((kk * 16 + a_row) * TS2 + jp * 16 + a_col) * 2;
                uint32_t vh0, vh1, vh2, vh3, vl0, vl1, vl2, vl3;
                LDSM_X4_T(vh0, vh1, vh2, vh3, sbase + BVh + off);
                LDSM_X4_T(vl0, vl1, vl2, vl3, sbase + BVl + off);
                MMA_BF16(o[2 * jp],     ph[0], ph[1], ph[2], ph[3], vh0, vh1);
                MMA_BF16(o[2 * jp],     ph[0], ph[1], ph[2], ph[3], vl0, vl1);
                MMA_BF16(o[2 * jp],     pl[0], pl[1], pl[2], pl[3], vh0, vh1);
                MMA_BF16(o[2 * jp + 1], ph[0], ph[1], ph[2], ph[3], vh2, vh3);
                MMA_BF16(o[2 * jp + 1], ph[0], ph[1], ph[2], ph[3], vl2, vl3);
                MMA_BF16(o[2 * jp + 1], pl[0], pl[1], pl[2], pl[3], vh2, vh3);
            }
        }
    }

    // ---- epilogue ----
    const float i0 = 1.0f / l0, i1 = 1.0f / l1;
    const int grow = b * SEQ + qt * 64 + 16 * wrp + g;
#pragma unroll
    for (int j = 0; j < 8; j++) {
        const int col = h * 64 + j * 8 + 2 * tig;
        *(float2*)(out + (size_t)grow * EMB + col) =
            make_float2(o[j][0] * i0, o[j][1] * i0);
        *(float2*)(out + (size_t)(grow + 8) * EMB + col) =
            make_float2(o[j][2] * i1, o[j][3] * i1);
    }
}

// ---------------------------------------------------------------------------
extern "C" void kernel_launch(void* const* d_in, const int* in_sizes, int n_in,
                              void* d_out, int out_size)
{
    const float* x    = (const float*)d_in[0];
    const float* w    = (const float*)d_in[1];
    const float* Wqkv = (const float*)d_in[2];
    const float* bqkv = (const float*)d_in[3];
    float* out = (float*)d_out;

    cudaFuncSetAttribute(qkv_gemm,
                         cudaFuncAttributeMaxDynamicSharedMemorySize,
                         GEMM_SMEM_BYTES);
    cudaFuncSetAttribute(attn_bf16,
                         cudaFuncAttributeMaxDynamicSharedMemorySize,
                         ATTN_SMEM_BYTES);

    split_x_kernel<<<MROWS * EMB / 4 / 256, 256>>>((const float4*)x);
    split_w_kernel<<<EMB * QKVN / 4 / 256, 256>>>((const float4*)Wqkv);

    dim3 g1(QKVN / 128, MROWS / 128);            // (24, 32)
    qkv_gemm<<<g1, 256, GEMM_SMEM_BYTES>>>(bqkv);

    dim3 g2(SEQ / 64, NHEAD, BATCH);             // (32, 16, 2)
    attn_bf16<<<g2, 128, ATTN_SMEM_BYTES>>>(w, out);
}

// round 4
// speedup vs baseline: 2.5485x; 1.0905x over previous
#include <cuda_runtime.h>
#include <cuda_bf16.h>
#include <math.h>
#include <stdint.h>

// Problem constants
#define BATCH   2
#define SEQ     2048
#define EMB     1024
#define NHEAD   16
#define QKVN    3072
#define MROWS   4096
#define TINY_F  1.17549435e-38f
#define SCALE_Q 0.125f
#define BIGNEG  -9000000000000000.0f
#define BIGPOS   9000000000000000.0f

// Global scratch
__device__ __nv_bfloat16 g_x_hi[(size_t)MROWS * EMB];
__device__ __nv_bfloat16 g_x_lo[(size_t)MROWS * EMB];
__device__ __nv_bfloat16 g_w_hi[(size_t)EMB * QKVN];
__device__ __nv_bfloat16 g_w_lo[(size_t)EMB * QKVN];
__device__ __nv_bfloat16 g_qkv_hi[(size_t)MROWS * QKVN];
__device__ __nv_bfloat16 g_qkv_lo[(size_t)MROWS * QKVN];
__device__ float g_wsc[BATCH * SEQ];
__device__ float g_wvl[BATCH * SEQ];

// ---------------------------------------------------------------------------
// PTX helpers
// ---------------------------------------------------------------------------
#define MMA_BF16(c, a0, a1, a2, a3, b0, b1)                                  \
    asm volatile(                                                            \
        "mma.sync.aligned.m16n8k16.row.col.f32.bf16.bf16.f32 "               \
        "{%0,%1,%2,%3}, {%4,%5,%6,%7}, {%8,%9}, {%0,%1,%2,%3};"              \
        : "+f"((c)[0]), "+f"((c)[1]), "+f"((c)[2]), "+f"((c)[3])             \
        : "r"(a0), "r"(a1), "r"(a2), "r"(a3), "r"(b0), "r"(b1))

#define LDSM_X4(r0, r1, r2, r3, a)                                           \
    asm volatile("ldmatrix.sync.aligned.m8n8.x4.shared.b16 {%0,%1,%2,%3}, [%4];" \
        : "=r"(r0), "=r"(r1), "=r"(r2), "=r"(r3) : "r"(a))

#define LDSM_X4_T(r0, r1, r2, r3, a)                                         \
    asm volatile("ldmatrix.sync.aligned.m8n8.x4.trans.shared.b16 {%0,%1,%2,%3}, [%4];" \
        : "=r"(r0), "=r"(r1), "=r"(r2), "=r"(r3) : "r"(a))

#define CPA16(dst_u32, src_ptr)                                              \
    asm volatile("cp.async.cg.shared.global [%0], [%1], 16;"                 \
                 :: "r"(dst_u32), "l"(src_ptr))
#define CPA_COMMIT() asm volatile("cp.async.commit_group;")
#define CPA_WAIT2()  asm volatile("cp.async.wait_group 2;")
#define CPA_WAIT1()  asm volatile("cp.async.wait_group 1;")
#define CPA_WAIT0()  asm volatile("cp.async.wait_group 0;")

__device__ __forceinline__ void split2(float x, float y,
                                       uint32_t& hi, uint32_t& lo)
{
    __nv_bfloat162 h = __floats2bfloat162_rn(x, y);
    float rx = x - __bfloat162float(h.x);
    float ry = y - __bfloat162float(h.y);
    __nv_bfloat162 l = __floats2bfloat162_rn(rx, ry);
    hi = *reinterpret_cast<uint32_t*>(&h);
    lo = *reinterpret_cast<uint32_t*>(&l);
}

// ---------------------------------------------------------------------------
// Prep kernels
// ---------------------------------------------------------------------------
__device__ __forceinline__ void split_store(const float4* in, uint2* hi,
                                            uint2* lo, int i)
{
    float4 v = in[i];
    uint2 uh, ul;
    split2(v.x, v.y, uh.x, ul.x);
    split2(v.z, v.w, uh.y, ul.y);
    hi[i] = uh;
    lo[i] = ul;
}

__global__ void split_x_kernel(const float4* __restrict__ in)
{
    int i = blockIdx.x * blockDim.x + threadIdx.x;
    if (i < MROWS * EMB / 4)
        split_store(in, (uint2*)g_x_hi, (uint2*)g_x_lo, i);
}

__global__ void split_w_kernel(const float4* __restrict__ in)
{
    int i = blockIdx.x * blockDim.x + threadIdx.x;
    if (i < EMB * QKVN / 4)
        split_store(in, (uint2*)g_w_hi, (uint2*)g_w_lo, i);
}

__global__ void wprep_kernel(const float* __restrict__ w)
{
    int i = blockIdx.x * blockDim.x + threadIdx.x;
    if (i < BATCH * SEQ) {
        const float v = w[i];
        const bool z = (v == 0.0f), on = (v == 1.0f);
        g_wsc[i] = (z || on) ? 0.0f : SCALE_Q;
        g_wvl[i] = z ? BIGNEG : (on ? BIGPOS : logf(v + TINY_F));
    }
}

// ---------------------------------------------------------------------------
// Kernel 1: qkv = x @ W + b, bf16x3 mma. CTA 128x128, BK=32, 256 threads.
// 3-slot cp.async ring, single barrier per k-tile.
// ---------------------------------------------------------------------------
#define GA_STR 40
#define GB_STR 136
#define GA_H   (128 * GA_STR)           // 5120 halves
#define GB_H   (32 * GB_STR)            // 4352 halves
#define GSLOT_B ((2 * GA_H + 2 * GB_H) * 2)   // 37888 bytes per slot
#define GEMM_SMEM_BYTES (3 * GSLOT_B)          // 113664

__global__ void __launch_bounds__(256)
qkv_gemm(const float* __restrict__ bias)
{
    extern __shared__ __nv_bfloat16 sh[];
    const uint32_t sbase = (uint32_t)__cvta_generic_to_shared(sh);

    const int tid  = threadIdx.x;
    const int lane = tid & 31, wid = tid >> 5;
    const int g = lane >> 2, tig = lane & 3;
    const int wr = wid >> 1, wc = wid & 1;
    const int bn = blockIdx.x * 128, bm = blockIdx.y * 128;

    const uint32_t OAh = 0, OAl = GA_H * 2;
    const uint32_t OBh = 2 * GA_H * 2, OBl = (2 * GA_H + GB_H) * 2;

    float acc[2][8][4];
#pragma unroll
    for (int mt = 0; mt < 2; mt++)
#pragma unroll
        for (int j = 0; j < 8; j++)
#pragma unroll
            for (int q = 0; q < 4; q++) acc[mt][j][q] = 0.0f;

    const int a_row = (lane & 7) + 8 * ((lane >> 3) & 1);
    const int a_col = 8 * (lane >> 4);
    const int b_row = lane & 15;
    const int b_col = 8 * (lane >> 4);

#define GEMM_ISSUE(slot, kt)                                                 \
    do {                                                                     \
        const uint32_t sb = sbase + (uint32_t)(slot) * GSLOT_B;              \
        _Pragma("unroll")                                                    \
        for (int i = 0; i < 2; i++) {                                        \
            int ch = tid + 256 * i;                                          \
            int r = ch >> 2, sg = ch & 3;                                    \
            size_t go = (size_t)(bm + r) * EMB + (kt) * 32 + sg * 8;         \
            uint32_t d = sb + (uint32_t)(r * GA_STR + sg * 8) * 2;           \
            CPA16(d + OAh, g_x_hi + go);                                     \
            CPA16(d + OAl, g_x_lo + go);                                     \
        }                                                                    \
        _Pragma("unroll")                                                    \
        for (int i = 0; i < 2; i++) {                                        \
            int ch = tid + 256 * i;                                          \
            int r = ch >> 4, sg = ch & 15;                                   \
            size_t go = (size_t)((kt) * 32 + r) * QKVN + bn + sg * 8;        \
            uint32_t d = sb + (uint32_t)(r * GB_STR + sg * 8) * 2;           \
            CPA16(d + OBh, g_w_hi + go);                                     \
            CPA16(d + OBl, g_w_lo + go);                                     \
        }                                                                    \
    } while (0)

    GEMM_ISSUE(0, 0);
    CPA_COMMIT();

    for (int kt = 0; kt < 32; kt++) {
        const int slot = kt % 3;
        if (kt < 31) {
            GEMM_ISSUE((kt + 1) % 3, kt + 1);
            CPA_COMMIT();
            CPA_WAIT1();
        } else {
            CPA_WAIT0();
        }
        __syncthreads();   // tile kt visible to all; slot reuse safe by ring depth 3

        const uint32_t sb = sbase + (uint32_t)slot * GSLOT_B;
#pragma unroll
        for (int ks = 0; ks < 2; ks++) {
            const int k0 = ks * 16;
            uint32_t ah[2][4], al[2][4];
#pragma unroll
            for (int mt = 0; mt < 2; mt++) {
                const uint32_t off =
                    (uint32_t)((wr * 32 + mt * 16 + a_row) * GA_STR + k0 + a_col) * 2;
                LDSM_X4(ah[mt][0], ah[mt][1], ah[mt][2], ah[mt][3], sb + OAh + off);
                LDSM_X4(al[mt][0], al[mt][1], al[mt][2], al[mt][3], sb + OAl + off);
            }
#pragma unroll
            for (int jp = 0; jp < 4; jp++) {
                const uint32_t off =
                    (uint32_t)((k0 + b_row) * GB_STR + wc * 64 + jp * 16 + b_col) * 2;
                uint32_t bh0, bh1, bh2, bh3, bl0, bl1, bl2, bl3;
                LDSM_X4_T(bh0, bh1, bh2, bh3, sb + OBh + off);
                LDSM_X4_T(bl0, bl1, bl2, bl3, sb + OBl + off);
#pragma unroll
                for (int mt = 0; mt < 2; mt++) {
                    MMA_BF16(acc[mt][2 * jp], ah[mt][0], ah[mt][1], ah[mt][2], ah[mt][3], bh0, bh1);
                    MMA_BF16(acc[mt][2 * jp], ah[mt][0], ah[mt][1], ah[mt][2], ah[mt][3], bl0, bl1);
                    MMA_BF16(acc[mt][2 * jp], al[mt][0], al[mt][1], al[mt][2], al[mt][3], bh0, bh1);
                    MMA_BF16(acc[mt][2 * jp + 1], ah[mt][0], ah[mt][1], ah[mt][2], ah[mt][3], bh2, bh3);
                    MMA_BF16(acc[mt][2 * jp + 1], ah[mt][0], ah[mt][1], ah[mt][2], ah[mt][3], bl2, bl3);
                    MMA_BF16(acc[mt][2 * jp + 1], al[mt][0], al[mt][1], al[mt][2], al[mt][3], bh2, bh3);
                }
            }
        }
    }

    // Epilogue: add bias, split to hi/lo bf16, store
#pragma unroll
    for (int mt = 0; mt < 2; mt++) {
        const int row0 = bm + wr * 32 + mt * 16 + g;
#pragma unroll
        for (int j = 0; j < 8; j++) {
            const int col = bn + wc * 64 + j * 8 + 2 * tig;
            const float2 bb = *(const float2*)(bias + col);
            uint32_t h0, l0, h1, l1;
            split2(acc[mt][j][0] + bb.x, acc[mt][j][1] + bb.y, h0, l0);
            split2(acc[mt][j][2] + bb.x, acc[mt][j][3] + bb.y, h1, l1);
            *(uint32_t*)(g_qkv_hi + (size_t)row0 * QKVN + col)       = h0;
            *(uint32_t*)(g_qkv_lo + (size_t)row0 * QKVN + col)       = l0;
            *(uint32_t*)(g_qkv_hi + (size_t)(row0 + 8) * QKVN + col) = h1;
            *(uint32_t*)(g_qkv_lo + (size_t)(row0 + 8) * QKVN + col) = l1;
        }
    }
#undef GEMM_ISSUE
}

// ---------------------------------------------------------------------------
// Kernel 2: flash attention, bf16x3 mma. Grid (S/128, H, B), 256 threads
// (8 warps, each owns 16 query rows of a 128-query tile).
// K/V in a 3-slot cp.async ring with depth-1 prefetch; ONE barrier per tile.
// w logit coefs staged wholly in smem at prologue.
// ---------------------------------------------------------------------------
#define ATS      72                            // halves per smem row
#define QTILE_B  (128 * ATS * 2)               // 18432
#define KTILE_B  (64 * ATS * 2)                // 9216
#define BQh      0
#define BQl      QTILE_B
#define KVBASE   (2 * QTILE_B)                 // 36864
#define SLOT_B   (4 * KTILE_B)                 // 36864
#define OKh      0
#define OKl      KTILE_B
#define OVh      (2 * KTILE_B)
#define OVl      (3 * KTILE_B)
#define WOFF     (KVBASE + 3 * SLOT_B)         // 147456
#define ATTN_SMEM_BYTES (WOFF + 2 * SEQ * 4)   // 163840

__global__ void __launch_bounds__(256)
attn_bf16(float* __restrict__ out)             // [B, S, E]
{
    extern __shared__ char shb[];
    const uint32_t sb = (uint32_t)__cvta_generic_to_shared(shb);
    const float* swsc = (const float*)(shb + WOFF);
    const float* swvl = swsc + SEQ;

    const int tid  = threadIdx.x;
    const int lane = tid & 31, wrp = tid >> 5;
    const int g = lane >> 2, tig = lane & 3;
    const int qt = blockIdx.x, h = blockIdx.y, b = blockIdx.z;

    const int a_row = (lane & 7) + 8 * ((lane >> 3) & 1);
    const int a_col = 8 * (lane >> 4);
    const int k_row = (lane & 7) + 8 * (lane >> 4);
    const int k_col = 8 * ((lane >> 3) & 1);

#define KV_ISSUE(slot, tt)                                                   \
    do {                                                                     \
        const uint32_t kbase = sb + KVBASE + (uint32_t)(slot) * SLOT_B;      \
        _Pragma("unroll")                                                    \
        for (int i = 0; i < 2; i++) {                                        \
            int ch = tid + 256 * i;                                          \
            int r = ch >> 3, sg = ch & 7;                                    \
            size_t go = (size_t)(b * SEQ + (tt) * 64 + r) * QKVN + h * 192 + sg * 8; \
            uint32_t d = (uint32_t)(r * ATS + sg * 8) * 2;                   \
            CPA16(kbase + OKh + d, g_qkv_hi + go + 64);                      \
            CPA16(kbase + OKl + d, g_qkv_lo + go + 64);                      \
            CPA16(kbase + OVh + d, g_qkv_hi + go + 128);                     \
            CPA16(kbase + OVl + d, g_qkv_lo + go + 128);                     \
        }                                                                    \
    } while (0)

    // ---- prologue: Q tile + w row (group 0), KV tile 0 (group 1) ----
#pragma unroll
    for (int i = 0; i < 4; i++) {
        const int ch = tid + 256 * i;
        const int r = ch >> 3, sg = ch & 7;
        const size_t go = (size_t)(b * SEQ + qt * 128 + r) * QKVN + h * 192 + sg * 8;
        const uint32_t d = (uint32_t)(r * ATS + sg * 8) * 2;
        CPA16(sb + BQh + d, g_qkv_hi + go);
        CPA16(sb + BQl + d, g_qkv_lo + go);
    }
#pragma unroll
    for (int i = 0; i < 2; i++) {
        const int ch = tid + 256 * i;   // 0..511
        CPA16(sb + WOFF + ch * 16, g_wsc + b * SEQ + ch * 4);
        CPA16(sb + WOFF + SEQ * 4 + ch * 16, g_wvl + b * SEQ + ch * 4);
    }
    CPA_COMMIT();
    KV_ISSUE(0, 0);
    CPA_COMMIT();
    CPA_WAIT1();        // Q + w landed
    __syncthreads();

    // Q fragments -> registers (loop invariant)
    uint32_t qh[4][4], ql[4][4];
#pragma unroll
    for (int kk = 0; kk < 4; kk++) {
        const uint32_t off =
            (uint32_t)((16 * wrp + a_row) * ATS + kk * 16 + a_col) * 2;
        LDSM_X4(qh[kk][0], qh[kk][1], qh[kk][2], qh[kk][3], sb + BQh + off);
        LDSM_X4(ql[kk][0], ql[kk][1], ql[kk][2], ql[kk][3], sb + BQl + off);
    }

    float m0 = -1e30f, m1 = -1e30f, l0 = 0.0f, l1 = 0.0f;
    float o[8][4];
#pragma unroll
    for (int j = 0; j < 8; j++)
        o[j][0] = o[j][1] = o[j][2] = o[j][3] = 0.0f;

    for (int t = 0; t < SEQ / 64; t++) {
        const int slot = t % 3;
        // prefetch t+1 into slot (t+1)%3 == (t-2)%3: its last readers finished
        // before barrier(t-1), which every thread has passed. Safe w/ 1 barrier.
        if (t + 1 < SEQ / 64) {
            KV_ISSUE((t + 1) % 3, t + 1);
            CPA_COMMIT();
            CPA_WAIT1();        // tile t's group complete (only t+1 pending)
        } else {
            CPA_WAIT0();
        }
        __syncthreads();        // tile t visible to every warp

        const uint32_t kb = sb + KVBASE + (uint32_t)slot * SLOT_B;

        // ---- S = Q K^T (bf16x3) ----
        float s[8][4];
#pragma unroll
        for (int j = 0; j < 8; j++)
            s[j][0] = s[j][1] = s[j][2] = s[j][3] = 0.0f;

#pragma unroll
        for (int kk = 0; kk < 4; kk++) {
#pragma unroll
            for (int jp = 0; jp < 4; jp++) {
                const uint32_t off =
                    (uint32_t)((jp * 16 + k_row) * ATS + kk * 16 + k_col) * 2;
                uint32_t kh0, kh1, kh2, kh3, kl0, kl1, kl2, kl3;
                LDSM_X4(kh0, kh1, kh2, kh3, kb + OKh + off);
                LDSM_X4(kl0, kl1, kl2, kl3, kb + OKl + off);
                MMA_BF16(s[2 * jp],     qh[kk][0], qh[kk][1], qh[kk][2], qh[kk][3], kh0, kh1);
                MMA_BF16(s[2 * jp],     qh[kk][0], qh[kk][1], qh[kk][2], qh[kk][3], kl0, kl1);
                MMA_BF16(s[2 * jp],     ql[kk][0], ql[kk][1], ql[kk][2], ql[kk][3], kh0, kh1);
                MMA_BF16(s[2 * jp + 1], qh[kk][0], qh[kk][1], qh[kk][2], qh[kk][3], kh2, kh3);
                MMA_BF16(s[2 * jp + 1], qh[kk][0], qh[kk][1], qh[kk][2], qh[kk][3], kl2, kl3);
                MMA_BF16(s[2 * jp + 1], ql[kk][0], ql[kk][1], ql[kk][2], ql[kk][3], kh2, kh3);
            }
        }

        // ---- logit transform + online softmax (fp32, w coefs from smem) ----
        const int wbase = t * 64;
        float mx0 = -1e30f, mx1 = -1e30f;
#pragma unroll
        for (int j = 0; j < 8; j++) {
            const float2 ws = *(const float2*)&swsc[wbase + j * 8 + 2 * tig];
            const float2 wv = *(const float2*)&swvl[wbase + j * 8 + 2 * tig];
            s[j][0] = fmaf(s[j][0], ws.x, wv.x);
            s[j][1] = fmaf(s[j][1], ws.y, wv.y);
            s[j][2] = fmaf(s[j][2], ws.x, wv.x);
            s[j][3] = fmaf(s[j][3], ws.y, wv.y);
            mx0 = fmaxf(mx0, fmaxf(s[j][0], s[j][1]));
            mx1 = fmaxf(mx1, fmaxf(s[j][2], s[j][3]));
        }
        mx0 = fmaxf(mx0, __shfl_xor_sync(0xffffffffu, mx0, 1));
        mx0 = fmaxf(mx0, __shfl_xor_sync(0xffffffffu, mx0, 2));
        mx1 = fmaxf(mx1, __shfl_xor_sync(0xffffffffu, mx1, 1));
        mx1 = fmaxf(mx1, __shfl_xor_sync(0xffffffffu, mx1, 2));

        const float mn0 = fmaxf(m0, mx0), mn1 = fmaxf(m1, mx1);
        const float c0 = __expf(m0 - mn0), c1 = __expf(m1 - mn1);
        m0 = mn0; m1 = mn1;

        float rs0 = 0.0f, rs1 = 0.0f;
#pragma unroll
        for (int j = 0; j < 8; j++) {
            s[j][0] = __expf(s[j][0] - m0);
            s[j][1] = __expf(s[j][1] - m0);
            s[j][2] = __expf(s[j][2] - m1);
            s[j][3] = __expf(s[j][3] - m1);
            rs0 += s[j][0] + s[j][1];
            rs1 += s[j][2] + s[j][3];
        }
        rs0 += __shfl_xor_sync(0xffffffffu, rs0, 1);
        rs0 += __shfl_xor_sync(0xffffffffu, rs0, 2);
        rs1 += __shfl_xor_sync(0xffffffffu, rs1, 1);
        rs1 += __shfl_xor_sync(0xffffffffu, rs1, 2);

        l0 = l0 * c0 + rs0;
        l1 = l1 * c1 + rs1;
#pragma unroll
        for (int j = 0; j < 8; j++) {
            o[j][0] *= c0; o[j][1] *= c0;
            o[j][2] *= c1; o[j][3] *= c1;
        }

        // ---- O += P V (bf16x3; P packed register-to-register) ----
#pragma unroll
        for (int kk = 0; kk < 4; kk++) {
            uint32_t ph[4], pl[4];
            split2(s[2 * kk][0],     s[2 * kk][1],     ph[0], pl[0]);
            split2(s[2 * kk][2],     s[2 * kk][3],     ph[1], pl[1]);
            split2(s[2 * kk + 1][0], s[2 * kk + 1][1], ph[2], pl[2]);
            split2(s[2 * kk + 1][2], s[2 * kk + 1][3], ph[3], pl[3]);
#pragma unroll
            for (int jp = 0; jp < 4; jp++) {
                const uint32_t off =
                    (uint32_t)((kk * 16 + a_row) * ATS + jp * 16 + a_col) * 2;
                uint32_t vh0, vh1, vh2, vh3, vl0, vl1, vl2, vl3;
                LDSM_X4_T(vh0, vh1, vh2, vh3, kb + OVh + off);
                LDSM_X4_T(vl0, vl1, vl2, vl3, kb + OVl + off);
                MMA_BF16(o[2 * jp],     ph[0], ph[1], ph[2], ph[3], vh0, vh1);
                MMA_BF16(o[2 * jp],     ph[0], ph[1], ph[2], ph[3], vl0, vl1);
                MMA_BF16(o[2 * jp],     pl[0], pl[1], pl[2], pl[3], vh0, vh1);
                MMA_BF16(o[2 * jp + 1], ph[0], ph[1], ph[2], ph[3], vh2, vh3);
                MMA_BF16(o[2 * jp + 1], ph[0], ph[1], ph[2], ph[3], vl2, vl3);
                MMA_BF16(o[2 * jp + 1], pl[0], pl[1], pl[2], pl[3], vh2, vh3);
            }
        }
    }

    // ---- epilogue ----
    const float i0 = 1.0f / l0, i1 = 1.0f / l1;
    const int grow = b * SEQ + qt * 128 + 16 * wrp + g;
#pragma unroll
    for (int j = 0; j < 8; j++) {
        const int col = h * 64 + j * 8 + 2 * tig;
        *(float2*)(out + (size_t)grow * EMB + col) =
            make_float2(o[j][0] * i0, o[j][1] * i0);
        *(float2*)(out + (size_t)(grow + 8) * EMB + col) =
            make_float2(o[j][2] * i1, o[j][3] * i1);
    }
#undef KV_ISSUE
}

// ---------------------------------------------------------------------------
extern "C" void kernel_launch(void* const* d_in, const int* in_sizes, int n_in,
                              void* d_out, int out_size)
{
    const float* x    = (const float*)d_in[0];
    const float* w    = (const float*)d_in[1];
    const float* Wqkv = (const float*)d_in[2];
    const float* bqkv = (const float*)d_in[3];
    float* out = (float*)d_out;

    cudaFuncSetAttribute(qkv_gemm,
                         cudaFuncAttributeMaxDynamicSharedMemorySize,
                         GEMM_SMEM_BYTES);
    cudaFuncSetAttribute(attn_bf16,
                         cudaFuncAttributeMaxDynamicSharedMemorySize,
                         ATTN_SMEM_BYTES);

    split_x_kernel<<<MROWS * EMB / 4 / 256, 256>>>((const float4*)x);
    split_w_kernel<<<EMB * QKVN / 4 / 256, 256>>>((const float4*)Wqkv);
    wprep_kernel<<<(BATCH * SEQ + 255) / 256, 256>>>(w);

    dim3 g1(QKVN / 128, MROWS / 128);            // (24, 32)
    qkv_gemm<<<g1, 256, GEMM_SMEM_BYTES>>>(bqkv);

    dim3 g2(SEQ / 128, NHEAD, BATCH);            // (16, 16, 2)
    attn_bf16<<<g2, 256, ATTN_SMEM_BYTES>>>(out);
}